// round 15
// baseline (speedup 1.0000x reference)
#include <cuda_runtime.h>

// MultiHeadAttention: B=4096, S=102, HIDDEN=8, HEADS=2, HEAD_DIM=4
// Query-pair packed attention: K stored dim-duplicated in smem so one
// mul2+3*fma2 chain produces TWO queries' dots packed (no cross-add).
// NB=7, NT=448, smem 104.6KB -> 2 CTAs/SM, grid=586 -> 1.98 waves.

#define SQ   102
#define NB   7
#define NT   448
#define RS   28                    // floats per j-row (both heads, padded)

typedef unsigned long long u64;

__device__ __forceinline__ u64 pack2(float lo, float hi) {
    u64 r; asm("mov.b64 %0, {%1, %2};" : "=l"(r) : "f"(lo), "f"(hi)); return r;
}
__device__ __forceinline__ void unpack2(u64 v, float& lo, float& hi) {
    asm("mov.b64 {%0, %1}, %2;" : "=f"(lo), "=f"(hi) : "l"(v));
}
__device__ __forceinline__ u64 fma2(u64 a, u64 b, u64 c) {
    u64 d; asm("fma.rn.f32x2 %0, %1, %2, %3;" : "=l"(d) : "l"(a), "l"(b), "l"(c)); return d;
}
__device__ __forceinline__ u64 mul2(u64 a, u64 b) {
    u64 d; asm("mul.rn.f32x2 %0, %1, %2;" : "=l"(d) : "l"(a), "l"(b)); return d;
}
__device__ __forceinline__ u64 add2(u64 a, u64 b) {
    u64 d; asm("add.rn.f32x2 %0, %1, %2;" : "=l"(d) : "l"(a), "l"(b)); return d;
}
__device__ __forceinline__ float ex2f(float x) {
    float r; asm("ex2.approx.f32 %0, %1;" : "=f"(r) : "f"(x)); return r;
}

// dual 8-dot: d0 = x . w[row 2p], d1 = x . w[row 2p+1]; w rows are 4 u64 each.
__device__ __forceinline__ void dual_dot8(const u64* w, u64 xax, u64 xay,
                                          u64 xbx, u64 xby, float& d0, float& d1)
{
    u64 a0 = mul2(xax, w[0]);
    a0 = fma2(xay, w[1], a0);
    a0 = fma2(xbx, w[2], a0);
    a0 = fma2(xby, w[3], a0);
    u64 a1 = mul2(xax, w[4]);
    a1 = fma2(xay, w[5], a1);
    a1 = fma2(xbx, w[6], a1);
    a1 = fma2(xby, w[7], a1);
    float l0, h0, l1, h1;
    unpack2(a0, l0, h0); unpack2(a1, l1, h1);
    d0 = l0 + h0; d1 = l1 + h1;
}

__global__ __launch_bounds__(NT, 2) void mha_fused_kernel(
    const float* __restrict__ query, const float* __restrict__ key,
    const float* __restrict__ value, const float* __restrict__ wq,
    const float* __restrict__ wk,    const float* __restrict__ wv,
    const float* __restrict__ wo,    float* __restrict__ out, int nbatch)
{
    extern __shared__ __align__(16) char smraw[];
    float (*sw)[64]     = (float (*)[64])smraw;                 // [4][64]        1024 B
    float (*ms)[2]      = (float (*)[2])(smraw + 1024);         // [102][2]        816 B
    float (*qs)[SQ][8]  = (float (*)[SQ][8])(smraw + 1840);     // [NB][102][8]  22848 B
    float (*kvs)[SQ*RS] = (float (*)[SQ*RS])(smraw + 24688);    // [NB][2856]    79968 B

    const int tid = threadIdx.x;
    const int b0  = blockIdx.x * NB;

    // ---- weights -> shared ----
    if (tid < 256) {
        int w = tid >> 6, e = tid & 63;
        const float* src = (w == 0) ? wq : (w == 1) ? wk : (w == 2) ? wv : wo;
        sw[w][e] = src[e];
    }
    // ---- rotary multipliers (Cody-Waite reduction, robust under fast-math) ----
    if (tid >= 256 && tid < 256 + SQ) {
        float x = (float)(tid - 256);
        float k = rintf(x * 0.15915494309189535f);
        float r = fmaf(-k, 6.28125f, x);
        r = fmaf(-k, 0.0019353071795864769f, r);
        float s, c; sincosf(r, &s, &c);
        ms[tid - 256][0] = s; ms[tid - 256][1] = c;
    }
    __syncthreads();

    // ---- projections + rotary; one thread = one full row (8 outputs) ----
    // exp arg = (q.k)*0.5 -> exp2((q.k)*0.5*log2e); fold C into q projection.
    // K written dim-duplicated: row j,head h: kdup[8] @ h*12, v[4] @ h*12+8.
    const float C = 0.72134752044448169f;   // 0.5 * log2(e)
    #pragma unroll
    for (int it = 0; it < 5; it++) {
        int i = tid + it * NT;
        if (i >= NB * 306) break;
        int nb  = i / 306;
        int rem = i - nb * 306;
        int b   = b0 + nb;
        if (b >= nbatch) continue;
        int t = rem / 102;                  // 0=q, 1=k, 2=v
        int s = rem - t * 102;
        const float* src = (t == 0) ? query : (t == 1) ? key : value;
        const ulonglong2* xr = (const ulonglong2*)(src + (size_t)b * 816 + s * 8);
        ulonglong2 xa = xr[0], xb = xr[1];
        float o[8];
        if (t < 2) {
            float msin = ms[s][0], mcos = ms[s][1];
            if (t == 0) { msin *= C; mcos *= C; }
            #pragma unroll
            for (int p = 0; p < 4; p++) {
                const u64* w = (const u64*)&sw[t][(2 * p) * 8];
                float d0, d1;
                dual_dot8(w, xa.x, xa.y, xb.x, xb.y, d0, d1);
                float m = (p < 2) ? msin : mcos;     // head0 -> sin, head1 -> cos
                o[2*p]   = (d0 - d1) * m;
                o[2*p+1] = (d1 + d0) * m;
            }
            if (t == 0) {
                float* dst = &qs[nb][s][0];
                *(float4*)dst       = make_float4(o[0], o[1], o[2], o[3]);
                *(float4*)(dst + 4) = make_float4(o[4], o[5], o[6], o[7]);
            } else {
                u64* r64 = (u64*)&kvs[nb][s * RS];
                r64[0] = pack2(o[0], o[0]); r64[1] = pack2(o[1], o[1]);
                r64[2] = pack2(o[2], o[2]); r64[3] = pack2(o[3], o[3]);
                r64[6] = pack2(o[4], o[4]); r64[7] = pack2(o[5], o[5]);
                r64[8] = pack2(o[6], o[6]); r64[9] = pack2(o[7], o[7]);
            }
        } else {
            #pragma unroll
            for (int p = 0; p < 4; p++) {
                const u64* w = (const u64*)&sw[2][(2 * p) * 8];
                dual_dot8(w, xa.x, xa.y, xb.x, xb.y, o[2*p], o[2*p+1]);
            }
            float* r = &kvs[nb][s * RS];
            *(float4*)(r + 8)  = make_float4(o[0], o[1], o[2], o[3]);
            *(float4*)(r + 20) = make_float4(o[4], o[5], o[6], o[7]);
        }
    }
    __syncthreads();

    // ---- attention: thread = (nb, head, 2 query-pairs); single-pass softmax ----
    if (tid < NB * 52) {
        int nb  = tid / 52;
        int rem = tid - nb * 52;
        int h   = (rem >= 26) ? 1 : 0;
        int qg  = rem - h * 26;
        int b   = b0 + nb;
        if (b < nbatch) {
            const int h4 = h * 4;
            const int q0 = qg * 4;
            const int q2 = (qg == 25) ? 100 : q0 + 2;  // last thread duplicates pair0
            float4 a0 = *(const float4*)&qs[nb][q0][h4];
            float4 a1 = *(const float4*)&qs[nb][q0 + 1][h4];
            float4 a2 = *(const float4*)&qs[nb][q2][h4];
            float4 a3 = *(const float4*)&qs[nb][q2 + 1][h4];
            u64 qp[2][4] = {
                { pack2(a0.x, a1.x), pack2(a0.y, a1.y), pack2(a0.z, a1.z), pack2(a0.w, a1.w) },
                { pack2(a2.x, a3.x), pack2(a2.y, a3.y), pack2(a2.z, a3.z), pack2(a2.w, a3.w) }
            };
            u64 acc[2][4] = {{0ull,0ull,0ull,0ull},{0ull,0ull,0ull,0ull}};
            u64 sum[2]    = {0ull, 0ull};
            const float* kvb = &kvs[nb][h * 12];
            #pragma unroll 2
            for (int j = 0; j < SQ; j++) {
                const u64* row = (const u64*)(kvb + j * RS);
                u64 kd0 = row[0], kd1 = row[1], kd2 = row[2], kd3 = row[3];
                ulonglong2 vv = *(const ulonglong2*)(row + 4);
                #pragma unroll
                for (int p = 0; p < 2; p++) {
                    u64 d = mul2(qp[p][0], kd0);
                    d = fma2(qp[p][1], kd1, d);
                    d = fma2(qp[p][2], kd2, d);
                    d = fma2(qp[p][3], kd3, d);
                    float da, db; unpack2(d, da, db);
                    float ea = ex2f(da), eb = ex2f(db);
                    sum[p] = add2(sum[p], pack2(ea, eb));
                    u64 ead = pack2(ea, ea), ebd = pack2(eb, eb);
                    acc[p][0] = fma2(ead, vv.x, acc[p][0]);
                    acc[p][1] = fma2(ead, vv.y, acc[p][1]);
                    acc[p][2] = fma2(ebd, vv.x, acc[p][2]);
                    acc[p][3] = fma2(ebd, vv.y, acc[p][3]);
                }
            }
            #pragma unroll
            for (int p = 0; p < 2; p++) {
                int rA = (p == 0) ? q0 : q2;
                float sA, sB; unpack2(sum[p], sA, sB);
                float ia = 1.0f / sA, ib = 1.0f / sB;
                float x0, x1, x2, x3;
                unpack2(acc[p][0], x0, x1); unpack2(acc[p][1], x2, x3);
                *(float4*)&qs[nb][rA][h4] = make_float4(x0*ia, x1*ia, x2*ia, x3*ia);
                unpack2(acc[p][2], x0, x1); unpack2(acc[p][3], x2, x3);
                *(float4*)&qs[nb][rA + 1][h4] = make_float4(x0*ib, x1*ib, x2*ib, x3*ib);
            }
        }
    }
    __syncthreads();

    // ---- output projection: one thread = one row; ao lives in qs ----
    #pragma unroll
    for (int it = 0; it < 2; it++) {
        int i = tid + it * NT;
        if (i >= NB * SQ) break;
        int nb = i / 102;
        int s  = i - nb * 102;
        int b  = b0 + nb;
        if (b >= nbatch) continue;
        const ulonglong2* xr = (const ulonglong2*)&qs[nb][s][0];
        ulonglong2 xa = xr[0], xb = xr[1];
        float o[8];
        #pragma unroll
        for (int p = 0; p < 4; p++) {
            const u64* w = (const u64*)&sw[3][(2 * p) * 8];
            dual_dot8(w, xa.x, xa.y, xb.x, xb.y, o[2*p], o[2*p+1]);
        }
        float4* dst = (float4*)(out + (size_t)b * 816 + s * 8);
        dst[0] = make_float4(o[0], o[1], o[2], o[3]);
        dst[1] = make_float4(o[4], o[5], o[6], o[7]);
    }
}

extern "C" void kernel_launch(void* const* d_in, const int* in_sizes, int n_in,
                              void* d_out, int out_size)
{
    const float* query = (const float*)d_in[0];
    const float* key   = (const float*)d_in[1];
    const float* value = (const float*)d_in[2];
    const float* wq    = (const float*)d_in[3];
    const float* wk    = (const float*)d_in[4];
    const float* wv    = (const float*)d_in[5];
    const float* wo    = (const float*)d_in[6];
    float* out = (float*)d_out;

    const int smem_bytes = 24688 + NB * SQ * RS * 4;   // 104656 B -> 2 CTAs/SM

    cudaFuncSetAttribute(mha_fused_kernel,
                         cudaFuncAttributeMaxDynamicSharedMemorySize, smem_bytes);

    int nbatch = in_sizes[0] / (SQ * 8);            // 4096
    int grid = (nbatch + NB - 1) / NB;              // 586
    mha_fused_kernel<<<grid, NT, smem_bytes>>>(query, key, value, wq, wk, wv, wo,
                                               out, nbatch);
}

// round 16
// speedup vs baseline: 1.0148x; 1.0148x over previous
#include <cuda_runtime.h>

// MultiHeadAttention: B=4096, S=102, HIDDEN=8, HEADS=2, HEAD_DIM=4
// Query-pair packed attention: K stored dim-duplicated in smem so one
// mul2+3*fma2 chain produces TWO queries' dots packed (no cross-add).
// NB=7, NT=448, smem 104.6KB -> 2 CTAs/SM, grid=586 -> 1.98 waves.

#define SQ   102
#define NB   7
#define NT   448
#define RS   28                    // floats per j-row (both heads, padded)

typedef unsigned long long u64;

__device__ __forceinline__ u64 pack2(float lo, float hi) {
    u64 r; asm("mov.b64 %0, {%1, %2};" : "=l"(r) : "f"(lo), "f"(hi)); return r;
}
__device__ __forceinline__ void unpack2(u64 v, float& lo, float& hi) {
    asm("mov.b64 {%0, %1}, %2;" : "=f"(lo), "=f"(hi) : "l"(v));
}
__device__ __forceinline__ u64 fma2(u64 a, u64 b, u64 c) {
    u64 d; asm("fma.rn.f32x2 %0, %1, %2, %3;" : "=l"(d) : "l"(a), "l"(b), "l"(c)); return d;
}
__device__ __forceinline__ u64 mul2(u64 a, u64 b) {
    u64 d; asm("mul.rn.f32x2 %0, %1, %2;" : "=l"(d) : "l"(a), "l"(b)); return d;
}
__device__ __forceinline__ u64 add2(u64 a, u64 b) {
    u64 d; asm("add.rn.f32x2 %0, %1, %2;" : "=l"(d) : "l"(a), "l"(b)); return d;
}
__device__ __forceinline__ float ex2f(float x) {
    float r; asm("ex2.approx.f32 %0, %1;" : "=f"(r) : "f"(x)); return r;
}

// dual 8-dot: d0 = x . w[row 2p], d1 = x . w[row 2p+1]; w rows are 4 u64 each.
__device__ __forceinline__ void dual_dot8(const u64* w, u64 xax, u64 xay,
                                          u64 xbx, u64 xby, float& d0, float& d1)
{
    u64 a0 = mul2(xax, w[0]);
    a0 = fma2(xay, w[1], a0);
    a0 = fma2(xbx, w[2], a0);
    a0 = fma2(xby, w[3], a0);
    u64 a1 = mul2(xax, w[4]);
    a1 = fma2(xay, w[5], a1);
    a1 = fma2(xbx, w[6], a1);
    a1 = fma2(xby, w[7], a1);
    float l0, h0, l1, h1;
    unpack2(a0, l0, h0); unpack2(a1, l1, h1);
    d0 = l0 + h0; d1 = l1 + h1;
}

__global__ __launch_bounds__(NT, 2) void mha_fused_kernel(
    const float* __restrict__ query, const float* __restrict__ key,
    const float* __restrict__ value, const float* __restrict__ wq,
    const float* __restrict__ wk,    const float* __restrict__ wv,
    const float* __restrict__ wo,    float* __restrict__ out, int nbatch)
{
    extern __shared__ __align__(16) char smraw[];
    float (*sw)[64]     = (float (*)[64])smraw;                 // [4][64]        1024 B
    float (*ms)[2]      = (float (*)[2])(smraw + 1024);         // [102][2]        816 B
    float (*qs)[SQ][8]  = (float (*)[SQ][8])(smraw + 1840);     // [NB][102][8]  22848 B
    float (*kvs)[SQ*RS] = (float (*)[SQ*RS])(smraw + 24688);    // [NB][2856]    79968 B

    const int tid = threadIdx.x;
    const int b0  = blockIdx.x * NB;

    // ---- weights -> shared ----
    if (tid < 256) {
        int w = tid >> 6, e = tid & 63;
        const float* src = (w == 0) ? wq : (w == 1) ? wk : (w == 2) ? wv : wo;
        sw[w][e] = src[e];
    }
    // ---- rotary multipliers (Cody-Waite reduction, robust under fast-math) ----
    if (tid >= 256 && tid < 256 + SQ) {
        float x = (float)(tid - 256);
        float k = rintf(x * 0.15915494309189535f);
        float r = fmaf(-k, 6.28125f, x);
        r = fmaf(-k, 0.0019353071795864769f, r);
        float s, c; sincosf(r, &s, &c);
        ms[tid - 256][0] = s; ms[tid - 256][1] = c;
    }
    __syncthreads();

    // ---- projections + rotary; one thread = one full row (8 outputs) ----
    // exp arg = (q.k)*0.5 -> exp2((q.k)*0.5*log2e); fold C into q projection.
    // K written dim-duplicated: row j,head h: kdup[8] @ h*12, v[4] @ h*12+8.
    const float C = 0.72134752044448169f;   // 0.5 * log2(e)
    #pragma unroll
    for (int it = 0; it < 5; it++) {
        int i = tid + it * NT;
        if (i >= NB * 306) break;
        int nb  = i / 306;
        int rem = i - nb * 306;
        int b   = b0 + nb;
        if (b >= nbatch) continue;
        int t = rem / 102;                  // 0=q, 1=k, 2=v
        int s = rem - t * 102;
        const float* src = (t == 0) ? query : (t == 1) ? key : value;
        const ulonglong2* xr = (const ulonglong2*)(src + (size_t)b * 816 + s * 8);
        ulonglong2 xa = xr[0], xb = xr[1];
        float o[8];
        if (t < 2) {
            float msin = ms[s][0], mcos = ms[s][1];
            if (t == 0) { msin *= C; mcos *= C; }
            #pragma unroll
            for (int p = 0; p < 4; p++) {
                const u64* w = (const u64*)&sw[t][(2 * p) * 8];
                float d0, d1;
                dual_dot8(w, xa.x, xa.y, xb.x, xb.y, d0, d1);
                float m = (p < 2) ? msin : mcos;     // head0 -> sin, head1 -> cos
                o[2*p]   = (d0 - d1) * m;
                o[2*p+1] = (d1 + d0) * m;
            }
            if (t == 0) {
                float* dst = &qs[nb][s][0];
                *(float4*)dst       = make_float4(o[0], o[1], o[2], o[3]);
                *(float4*)(dst + 4) = make_float4(o[4], o[5], o[6], o[7]);
            } else {
                u64* r64 = (u64*)&kvs[nb][s * RS];
                r64[0] = pack2(o[0], o[0]); r64[1] = pack2(o[1], o[1]);
                r64[2] = pack2(o[2], o[2]); r64[3] = pack2(o[3], o[3]);
                r64[6] = pack2(o[4], o[4]); r64[7] = pack2(o[5], o[5]);
                r64[8] = pack2(o[6], o[6]); r64[9] = pack2(o[7], o[7]);
            }
        } else {
            #pragma unroll
            for (int p = 0; p < 4; p++) {
                const u64* w = (const u64*)&sw[2][(2 * p) * 8];
                dual_dot8(w, xa.x, xa.y, xb.x, xb.y, o[2*p], o[2*p+1]);
            }
            float* r = &kvs[nb][s * RS];
            *(float4*)(r + 8)  = make_float4(o[0], o[1], o[2], o[3]);
            *(float4*)(r + 20) = make_float4(o[4], o[5], o[6], o[7]);
        }
    }
    __syncthreads();

    // ---- attention: thread = (nb, head, 2 query-pairs); single-pass softmax ----
    if (tid < NB * 52) {
        int nb  = tid / 52;
        int rem = tid - nb * 52;
        int h   = (rem >= 26) ? 1 : 0;
        int qg  = rem - h * 26;
        int b   = b0 + nb;
        if (b < nbatch) {
            const int h4 = h * 4;
            const int q0 = qg * 4;
            const int q2 = (qg == 25) ? 100 : q0 + 2;  // last thread duplicates pair0
            float4 a0 = *(const float4*)&qs[nb][q0][h4];
            float4 a1 = *(const float4*)&qs[nb][q0 + 1][h4];
            float4 a2 = *(const float4*)&qs[nb][q2][h4];
            float4 a3 = *(const float4*)&qs[nb][q2 + 1][h4];
            u64 qp[2][4] = {
                { pack2(a0.x, a1.x), pack2(a0.y, a1.y), pack2(a0.z, a1.z), pack2(a0.w, a1.w) },
                { pack2(a2.x, a3.x), pack2(a2.y, a3.y), pack2(a2.z, a3.z), pack2(a2.w, a3.w) }
            };
            u64 acc[2][4] = {{0ull,0ull,0ull,0ull},{0ull,0ull,0ull,0ull}};
            u64 sum[2]    = {0ull, 0ull};
            const float* kvb = &kvs[nb][h * 12];
            #pragma unroll 2
            for (int j = 0; j < SQ; j++) {
                const u64* row = (const u64*)(kvb + j * RS);
                u64 kd0 = row[0], kd1 = row[1], kd2 = row[2], kd3 = row[3];
                ulonglong2 vv = *(const ulonglong2*)(row + 4);
                #pragma unroll
                for (int p = 0; p < 2; p++) {
                    u64 d = mul2(qp[p][0], kd0);
                    d = fma2(qp[p][1], kd1, d);
                    d = fma2(qp[p][2], kd2, d);
                    d = fma2(qp[p][3], kd3, d);
                    float da, db; unpack2(d, da, db);
                    float ea = ex2f(da), eb = ex2f(db);
                    sum[p] = add2(sum[p], pack2(ea, eb));
                    u64 ead = pack2(ea, ea), ebd = pack2(eb, eb);
                    acc[p][0] = fma2(ead, vv.x, acc[p][0]);
                    acc[p][1] = fma2(ead, vv.y, acc[p][1]);
                    acc[p][2] = fma2(ebd, vv.x, acc[p][2]);
                    acc[p][3] = fma2(ebd, vv.y, acc[p][3]);
                }
            }
            #pragma unroll
            for (int p = 0; p < 2; p++) {
                int rA = (p == 0) ? q0 : q2;
                float sA, sB; unpack2(sum[p], sA, sB);
                float ia = 1.0f / sA, ib = 1.0f / sB;
                float x0, x1, x2, x3;
                unpack2(acc[p][0], x0, x1); unpack2(acc[p][1], x2, x3);
                *(float4*)&qs[nb][rA][h4] = make_float4(x0*ia, x1*ia, x2*ia, x3*ia);
                unpack2(acc[p][2], x0, x1); unpack2(acc[p][3], x2, x3);
                *(float4*)&qs[nb][rA + 1][h4] = make_float4(x0*ib, x1*ib, x2*ib, x3*ib);
            }
        }
    }
    __syncthreads();

    // ---- output projection: one thread = one row; ao lives in qs ----
    #pragma unroll
    for (int it = 0; it < 2; it++) {
        int i = tid + it * NT;
        if (i >= NB * SQ) break;
        int nb = i / 102;
        int s  = i - nb * 102;
        int b  = b0 + nb;
        if (b >= nbatch) continue;
        const ulonglong2* xr = (const ulonglong2*)&qs[nb][s][0];
        ulonglong2 xa = xr[0], xb = xr[1];
        float o[8];
        #pragma unroll
        for (int p = 0; p < 4; p++) {
            const u64* w = (const u64*)&sw[3][(2 * p) * 8];
            dual_dot8(w, xa.x, xa.y, xb.x, xb.y, o[2*p], o[2*p+1]);
        }
        float4* dst = (float4*)(out + (size_t)b * 816 + s * 8);
        dst[0] = make_float4(o[0], o[1], o[2], o[3]);
        dst[1] = make_float4(o[4], o[5], o[6], o[7]);
    }
}

extern "C" void kernel_launch(void* const* d_in, const int* in_sizes, int n_in,
                              void* d_out, int out_size)
{
    const float* query = (const float*)d_in[0];
    const float* key   = (const float*)d_in[1];
    const float* value = (const float*)d_in[2];
    const float* wq    = (const float*)d_in[3];
    const float* wk    = (const float*)d_in[4];
    const float* wv    = (const float*)d_in[5];
    const float* wo    = (const float*)d_in[6];
    float* out = (float*)d_out;

    const int smem_bytes = 24688 + NB * SQ * RS * 4;   // 104656 B -> 2 CTAs/SM

    cudaFuncSetAttribute(mha_fused_kernel,
                         cudaFuncAttributeMaxDynamicSharedMemorySize, smem_bytes);

    int nbatch = in_sizes[0] / (SQ * 8);            // 4096
    int grid = (nbatch + NB - 1) / NB;              // 586
    mha_fused_kernel<<<grid, NT, smem_bytes>>>(query, key, value, wq, wk, wv, wo,
                                               out, nbatch);
}